// round 9
// baseline (speedup 1.0000x reference)
#include <cuda_runtime.h>
#include <cuda_bf16.h>
#include <cstdint>
#include <math.h>

#define HDIM 96
#define WDIM 96
#define PIX  (HDIM*WDIM)     // 9216
#define NB   4
#define CINF 1024
#define CINT 512
#define DD   4
#define QD   9
#define QQ   81
#define NPIX (NB*PIX)        // 36864

// ------------------------- scratch (device globals) -------------------------
__device__ __nv_bfloat16 g_xT  [(size_t)NPIX * CINF];      // bf16 [p][1024]
__device__ __nv_bfloat16 g_xrT [(size_t)NPIX * CINF];      // bf16 [p][1024]
__device__ __nv_bfloat16 g_thb [(size_t)NPIX * CINT];      // bf16 theta NHWC [p][512]
__device__ __nv_bfloat16 g_gphib[(size_t)NPIX * 2 * CINT]; // bf16 g|phi NHWC [p][1024]
__device__ __nv_bfloat16 g_ybf [(size_t)NPIX * CINT];      // bf16 y NHWC [p][512]
__device__ __nv_bfloat16 g_wth [(size_t)CINT * CINF];
__device__ __nv_bfloat16 g_wgp [(size_t)CINF * CINF];      // (wg;wphi)
__device__ __nv_bfloat16 g_wo  [(size_t)CINF * CINT];

// ------------------------- helpers ------------------------------------------
__device__ __forceinline__ uint32_t smem_u32(const void* p) {
    uint32_t a;
    asm("{ .reg .u64 t; cvta.to.shared.u64 t, %1; cvt.u32.u64 %0, t; }" : "=r"(a) : "l"(p));
    return a;
}
#define CP_ASYNC16(dst, src) \
    asm volatile("cp.async.cg.shared.global [%0], [%1], 16;" :: "r"(dst), "l"(src))
#define CP_ASYNC16Z(dst, src, sz) \
    asm volatile("cp.async.cg.shared.global [%0], [%1], 16, %2;" :: "r"(dst), "l"(src), "r"(sz))
#define CP_COMMIT() asm volatile("cp.async.commit_group;" ::: "memory")
#define CP_WAIT(n)  asm volatile("cp.async.wait_group %0;" :: "n"(n) : "memory")

#define LDSM4(r, a) \
    asm volatile("ldmatrix.sync.aligned.m8n8.x4.shared.b16 {%0,%1,%2,%3}, [%4];" \
        : "=r"((r)[0]), "=r"((r)[1]), "=r"((r)[2]), "=r"((r)[3]) : "r"(a))
#define LDSM4T(r, a) \
    asm volatile("ldmatrix.sync.aligned.m8n8.x4.trans.shared.b16 {%0,%1,%2,%3}, [%4];" \
        : "=r"((r)[0]), "=r"((r)[1]), "=r"((r)[2]), "=r"((r)[3]) : "r"(a))

#define MMA16816(d, a, bb0, bb1) \
    asm volatile("mma.sync.aligned.m16n8k16.row.col.f32.bf16.bf16.f32 " \
        "{%0,%1,%2,%3},{%4,%5,%6,%7},{%8,%9},{%0,%1,%2,%3};" \
        : "+f"((d)[0]), "+f"((d)[1]), "+f"((d)[2]), "+f"((d)[3]) \
        : "r"((a)[0]), "r"((a)[1]), "r"((a)[2]), "r"((a)[3]), "r"(bb0), "r"(bb1))

// 32-bf16-wide tile swizzle (64B rows) — fused kernel phase 1
__device__ __forceinline__ uint32_t sw_off(int row, int ch) {
    return (uint32_t)(row * 64 + ((ch ^ ((row >> 1) & 3)) << 4));
}
// 64-bf16-wide tile swizzle (128B rows) — GEMM stages
__device__ __forceinline__ uint32_t sw128(int row, int ch) {
    return (uint32_t)(row * 128 + ((ch ^ (row & 7)) << 4));
}

// ------------------------- transpose + convert (x & x_ref merged) ------------
__global__ void conv_tr2_k(const float* __restrict__ x, const float* __restrict__ xr,
                           __nv_bfloat16* __restrict__ dx, __nv_bfloat16* __restrict__ dxr)
{
    __shared__ float ts[64][33];
    const int tx = threadIdx.x, ty = threadIdx.y;
    const int z = blockIdx.z;
    const int n = z & (NB - 1);
    const float* src = (z < NB) ? x : xr;
    __nv_bfloat16* dst = (z < NB) ? dx : dxr;
    const int p0 = blockIdx.x * 32, c0 = blockIdx.y * 64;
    #pragma unroll
    for (int r = 0; r < 8; r++) {
        int cl = ty + r * 8;
        ts[cl][tx] = src[((size_t)n * CINF + c0 + cl) * PIX + p0 + tx];
    }
    __syncthreads();
    #pragma unroll
    for (int r = 0; r < 4; r++) {
        int pl = ty + r * 8;
        __nv_bfloat162 v = __floats2bfloat162_rn(ts[2 * tx][pl], ts[2 * tx + 1][pl]);
        *(__nv_bfloat162*)(dst + ((size_t)n * PIX + p0 + pl) * CINF + c0 + 2 * tx) = v;
    }
}

// all four weight tensors are 524288 elements each
__global__ void cvt4_k(const float* __restrict__ s0, const float* __restrict__ s1,
                       const float* __restrict__ s2, const float* __restrict__ s3,
                       __nv_bfloat16* __restrict__ d0, __nv_bfloat16* __restrict__ d1,
                       __nv_bfloat16* __restrict__ d2, __nv_bfloat16* __restrict__ d3)
{
    int i = blockIdx.x * 256 + threadIdx.x;
    int seg = i >> 19, off = i & 524287;
    const float* s = (seg == 0) ? s0 : (seg == 1) ? s1 : (seg == 2) ? s2 : s3;
    __nv_bfloat16* d = (seg == 0) ? d0 : (seg == 1) ? d1 : (seg == 2) ? d2 : d3;
    d[off] = __float2bfloat16(s[off]);
}

// ------------------------- merged projection GEMM (128o x 256p) --------------
// blockIdx.y < 4 : theta = w_theta @ x   -> thb  [p][512]
// blockIdx.y >= 4: (g;phi) = wgp @ x_ref -> gphib [p][1024]
// K-chunk 64, 2-stage cp.async (96KB dyn smem), 8 warps (2x4), warp tile 64x64.
__global__ __launch_bounds__(256)
void proj_gemm(const __nv_bfloat16* __restrict__ wth, const __nv_bfloat16* __restrict__ wgp,
               const __nv_bfloat16* __restrict__ xT, const __nv_bfloat16* __restrict__ xrT,
               const float* __restrict__ bth, const float* __restrict__ bg,
               const float* __restrict__ bphi,
               __nv_bfloat16* __restrict__ thb, __nv_bfloat16* __restrict__ gphib)
{
    extern __shared__ char smem[];   // 2 x (A 16KB | B 32KB)

    const int t = threadIdx.x, lane = t & 31, wid = t >> 5;
    const int warp_m = wid >> 2, warp_n = wid & 3;
    const int n = blockIdx.z, pbase = blockIdx.x * 256;
    const int by = blockIdx.y;
    const bool th = (by < 4);
    const int obase = (th ? by : by - 4) * 128;
    const __nv_bfloat16* A  = th ? wth : wgp;
    const __nv_bfloat16* Bx = th ? xT : xrT;
    __nv_bfloat16* out = th ? thb : gphib;
    const int ldo = th ? CINT : 2 * CINT;
    const float* b0 = th ? bth : bg;
    const float* b1 = th ? bth : bphi;
    const int K = CINF, NC = K >> 6;   // 16

    const __nv_bfloat16* Ab = A + (size_t)obase * K;
    const __nv_bfloat16* Bb = Bx + ((size_t)n * PIX + pbase) * K;
    const uint32_t sbase = smem_u32(smem);

    float acc[4][8][4];
    #pragma unroll
    for (int mi = 0; mi < 4; mi++)
        #pragma unroll
        for (int ni = 0; ni < 8; ni++)
            #pragma unroll
            for (int r = 0; r < 4; r++) acc[mi][ni][r] = 0.f;

    const int rowL = t >> 3, chL = t & 7;
    auto issue = [&](int c) {
        const int k0 = c << 6;
        const uint32_t st = sbase + (c & 1) * 49152;
        #pragma unroll
        for (int i = 0; i < 4; i++) {
            int row = rowL + i * 32;
            CP_ASYNC16(st + sw128(row, chL), Ab + (size_t)row * K + k0 + chL * 8);
        }
        #pragma unroll
        for (int i = 0; i < 8; i++) {
            int row = rowL + i * 32;
            CP_ASYNC16(st + 16384 + sw128(row, chL), Bb + (size_t)row * K + k0 + chL * 8);
        }
        CP_COMMIT();
    };

    issue(0);
    const int rl = lane & 15, cs = lane >> 4;

    for (int c = 0; c < NC; c++) {
        CP_WAIT(0);
        __syncthreads();
        if (c + 1 < NC) issue(c + 1);

        const uint32_t stA = sbase + (c & 1) * 49152;
        const uint32_t stB = stA + 16384;
        #pragma unroll
        for (int kh = 0; kh < 4; kh++) {
            const int ch = 2 * kh + cs;
            uint32_t af[4][4], bf[4][4];
            #pragma unroll
            for (int mi = 0; mi < 4; mi++)
                LDSM4(af[mi], stA + sw128(warp_m * 64 + mi * 16 + rl, ch));
            #pragma unroll
            for (int g = 0; g < 4; g++)
                LDSM4(bf[g], stB + sw128(warp_n * 64 + g * 16 + rl, ch));
            #pragma unroll
            for (int mi = 0; mi < 4; mi++)
                #pragma unroll
                for (int g = 0; g < 4; g++) {
                    MMA16816(acc[mi][2 * g + 0], af[mi], bf[g][0], bf[g][2]);
                    MMA16816(acc[mi][2 * g + 1], af[mi], bf[g][1], bf[g][3]);
                }
        }
    }

    // epilogue: transpose via SMEM -> coalesced bf16 NHWC rows
    __syncthreads();
    __nv_bfloat16* S = (__nv_bfloat16*)smem;   // [256 p][136 o]
    #pragma unroll
    for (int mi = 0; mi < 4; mi++) {
        #pragma unroll
        for (int h = 0; h < 2; h++) {
            const int ol = warp_m * 64 + mi * 16 + (lane >> 2) + h * 8;
            const int og = obase + ol;
            const float bias = (og < CINT) ? b0[og] : b1[og - CINT];
            #pragma unroll
            for (int ni = 0; ni < 8; ni++) {
                const int pl = warp_n * 64 + ni * 8 + (lane & 3) * 2;
                S[(size_t)pl * 136 + ol]       = __float2bfloat16(acc[mi][ni][2 * h + 0] + bias);
                S[(size_t)(pl + 1) * 136 + ol] = __float2bfloat16(acc[mi][ni][2 * h + 1] + bias);
            }
        }
    }
    __syncthreads();
    #pragma unroll
    for (int s = 0; s < 32; s++) {
        const int pl = s * 8 + wid;
        uint2 v = *(uint2*)&S[(size_t)pl * 136 + lane * 4];
        *(uint2*)(out + ((size_t)n * PIX + pbase + pl) * ldo + obase + lane * 4) = v;
    }
}

// ------------------------- final GEMM (128o x 256p, residual, fp32 NCHW) -----
__global__ __launch_bounds__(256)
void final_gemm(const __nv_bfloat16* __restrict__ A, const __nv_bfloat16* __restrict__ B,
                const float* __restrict__ b0, float* __restrict__ out,
                const float* __restrict__ resid)
{
    extern __shared__ char smem[];   // 2 x 48KB

    const int t = threadIdx.x, lane = t & 31, wid = t >> 5;
    const int warp_m = wid >> 2, warp_n = wid & 3;
    const int n = blockIdx.z, pbase = blockIdx.x * 256, obase = blockIdx.y * 128;
    const int K = CINT, NC = K >> 6;   // 8

    const __nv_bfloat16* Ab = A + (size_t)obase * K;
    const __nv_bfloat16* Bb = B + ((size_t)n * PIX + pbase) * K;
    const uint32_t sbase = smem_u32(smem);

    float acc[4][8][4];
    #pragma unroll
    for (int mi = 0; mi < 4; mi++)
        #pragma unroll
        for (int ni = 0; ni < 8; ni++)
            #pragma unroll
            for (int r = 0; r < 4; r++) acc[mi][ni][r] = 0.f;

    const int rowL = t >> 3, chL = t & 7;
    auto issue = [&](int c) {
        const int k0 = c << 6;
        const uint32_t st = sbase + (c & 1) * 49152;
        #pragma unroll
        for (int i = 0; i < 4; i++) {
            int row = rowL + i * 32;
            CP_ASYNC16(st + sw128(row, chL), Ab + (size_t)row * K + k0 + chL * 8);
        }
        #pragma unroll
        for (int i = 0; i < 8; i++) {
            int row = rowL + i * 32;
            CP_ASYNC16(st + 16384 + sw128(row, chL), Bb + (size_t)row * K + k0 + chL * 8);
        }
        CP_COMMIT();
    };

    issue(0);
    const int rl = lane & 15, cs = lane >> 4;

    for (int c = 0; c < NC; c++) {
        CP_WAIT(0);
        __syncthreads();
        if (c + 1 < NC) issue(c + 1);

        const uint32_t stA = sbase + (c & 1) * 49152;
        const uint32_t stB = stA + 16384;
        #pragma unroll
        for (int kh = 0; kh < 4; kh++) {
            const int ch = 2 * kh + cs;
            uint32_t af[4][4], bf[4][4];
            #pragma unroll
            for (int mi = 0; mi < 4; mi++)
                LDSM4(af[mi], stA + sw128(warp_m * 64 + mi * 16 + rl, ch));
            #pragma unroll
            for (int g = 0; g < 4; g++)
                LDSM4(bf[g], stB + sw128(warp_n * 64 + g * 16 + rl, ch));
            #pragma unroll
            for (int mi = 0; mi < 4; mi++)
                #pragma unroll
                for (int g = 0; g < 4; g++) {
                    MMA16816(acc[mi][2 * g + 0], af[mi], bf[g][0], bf[g][2]);
                    MMA16816(acc[mi][2 * g + 1], af[mi], bf[g][1], bf[g][3]);
                }
        }
    }

    // epilogue: stage 64-o groups to SMEM, then coalesced resid add + store
    float* Es = (float*)smem;   // [64 o][260 p]
    #pragma unroll
    for (int og = 0; og < 2; og++) {
        __syncthreads();
        if (warp_m == og) {
            #pragma unroll
            for (int mi = 0; mi < 4; mi++)
                #pragma unroll
                for (int h = 0; h < 2; h++) {
                    const int row = mi * 16 + (lane >> 2) + h * 8;
                    #pragma unroll
                    for (int ni = 0; ni < 8; ni++) {
                        const int col = warp_n * 64 + ni * 8 + (lane & 3) * 2;
                        Es[(size_t)row * 260 + col]     = acc[mi][ni][2 * h + 0];
                        Es[(size_t)row * 260 + col + 1] = acc[mi][ni][2 * h + 1];
                    }
                }
        }
        __syncthreads();
        #pragma unroll
        for (int s = 0; s < 8; s++) {
            const int row = s * 8 + wid;
            const int o = obase + og * 64 + row;
            const float bias = b0[o];
            #pragma unroll
            for (int j = 0; j < 2; j++) {
                const int poff = j * 128 + lane * 4;
                const size_t addr = ((size_t)n * CINF + o) * PIX + pbase + poff;
                float4 e = *(float4*)&Es[(size_t)row * 260 + poff];
                float4 r = *(const float4*)(resid + addr);
                float4 v;
                v.x = e.x + bias + r.x; v.y = e.y + bias + r.y;
                v.z = e.z + bias + r.z; v.w = e.w + bias + r.w;
                *(float4*)(out + addr) = v;
            }
        }
    }
}

// ------------------------- fused corr + softmax + assemble -------------------
// (unchanged from R8 — passed twice)
__global__ __launch_bounds__(256, 2)
void fused_attn_k(const __nv_bfloat16* __restrict__ theta,
                  const __nv_bfloat16* __restrict__ gphi,
                  __nv_bfloat16* __restrict__ y)
{
    extern __shared__ char smem[];
    char*  Xr   = smem + 33792;
    float* Cs   = (float*)Xr;                       // [64][266] fp32
    float* invs = (float*)(smem + 33792 + 68096);   // [64]

    const int t = threadIdx.x, lane = t & 31, wid = t >> 5;
    const int warp_m = wid >> 2, warp_n = wid & 3;  // 2 x 4
    const int rl = lane & 15, cs = lane >> 4;
    const int n = blockIdx.z, h0 = blockIdx.y * 8, w0 = blockIdx.x * 8;

    const uint32_t sbX  = smem_u32(Xr);
    const uint32_t sbPW = smem_u32(smem);

    float acc[2][8][4];
    #pragma unroll
    for (int a = 0; a < 2; a++)
        #pragma unroll
        for (int b = 0; b < 8; b++)
            #pragma unroll
            for (int c = 0; c < 4; c++) acc[a][b][c] = 0.f;

    // ---------------- phase 1: corr GEMM ----------------
    const int rowA = t >> 2, chA = t & 3;
    const __nv_bfloat16* thsrc =
        theta + ((size_t)n * PIX + (h0 + (rowA >> 3)) * WDIM + (w0 + (rowA & 7))) * CINT + chA * 8;

    const __nv_bfloat16* phsrc[4];
    uint32_t phok[4]; int phrow[4], phch[4];
    #pragma unroll
    for (int i = 0; i < 4; i++) {
        int idx = t + i * 256;
        int row = idx >> 2, ch = idx & 3;
        int hy = h0 + (row >> 4) - DD, hx = w0 + (row & 15) - DD;
        bool ok = (hy >= 0 && hy < HDIM && hx >= 0 && hx < WDIM);
        phrow[i] = row; phch[i] = ch; phok[i] = ok ? 16u : 0u;
        phsrc[i] = gphi + (ok ? (((size_t)n * PIX + hy * WDIM + hx) * 1024 + 512 + ch * 8) : 0);
    }

    auto issue1 = [&](int c) {
        const int c0 = c << 5;
        const uint32_t st = sbX + (c % 3) * 20480;
        CP_ASYNC16(st + sw_off(rowA, chA), thsrc + c0);
        #pragma unroll
        for (int i = 0; i < 4; i++)
            CP_ASYNC16Z(st + 4096 + sw_off(phrow[i], phch[i]),
                        phsrc[i] + (phok[i] ? c0 : 0), phok[i]);
        CP_COMMIT();
    };

    issue1(0); issue1(1);
    for (int c = 0; c < 16; c++) {
        if (c < 15) CP_WAIT(1); else CP_WAIT(0);
        __syncthreads();
        if (c + 2 < 16) issue1(c + 2);
        const uint32_t stA = sbX + (c % 3) * 20480;
        const uint32_t stB = stA + 4096;
        #pragma unroll
        for (int kh = 0; kh < 2; kh++) {
            const int ch = 2 * kh + cs;
            uint32_t af[2][4], bm[4][4];
            #pragma unroll
            for (int mi = 0; mi < 2; mi++)
                LDSM4(af[mi], stA + sw_off(warp_m * 32 + mi * 16 + rl, ch));
            #pragma unroll
            for (int nf = 0; nf < 4; nf++)
                LDSM4(bm[nf], stB + sw_off(warp_n * 64 + nf * 16 + rl, ch));
            #pragma unroll
            for (int mi = 0; mi < 2; mi++)
                #pragma unroll
                for (int nf = 0; nf < 4; nf++) {
                    MMA16816(acc[mi][2 * nf + 0], af[mi], bm[nf][0], bm[nf][2]);
                    MMA16816(acc[mi][2 * nf + 1], af[mi], bm[nf][1], bm[nf][3]);
                }
        }
    }
    __syncthreads();   // stages dead; write C to smem (overlays stage region)

    #pragma unroll
    for (int mi = 0; mi < 2; mi++)
        #pragma unroll
        for (int ni = 0; ni < 8; ni++) {
            const int r0  = warp_m * 32 + mi * 16 + (lane >> 2);
            const int col = warp_n * 64 + ni * 8 + 2 * (lane & 3);
            *(float2*)&Cs[(size_t)r0 * 266 + col]       = make_float2(acc[mi][ni][0], acc[mi][ni][1]);
            *(float2*)&Cs[(size_t)(r0 + 8) * 266 + col] = make_float2(acc[mi][ni][2], acc[mi][ni][3]);
        }
    __syncthreads();

    // ---------------- phase 2: softmax -> PW bf16 ----------------
    if (t < 64) {
        const int py = t >> 3, pxx = t & 7;
        uint32_t* pwz = (uint32_t*)(smem + t * 528);
        #pragma unroll 4
        for (int i = 0; i < 132; i++) pwz[i] = 0;
        const float SC = 0.051031036307982884f;   // 256/(512*sqrt(96))
        float m = -1e30f;
        #pragma unroll
        for (int dy = 0; dy < QD; dy++)
            #pragma unroll
            for (int dx = 0; dx < QD; dx++)
                m = fmaxf(m, Cs[(size_t)t * 266 + (py + dy) * 16 + pxx + dx] * SC);
        float s = 0.f;
        __nv_bfloat16* pwrow = (__nv_bfloat16*)(smem + t * 528);
        #pragma unroll
        for (int dy = 0; dy < QD; dy++)
            #pragma unroll
            for (int dx = 0; dx < QD; dx++) {
                const int col = (py + dy) * 16 + pxx + dx;
                float e = __expf(Cs[(size_t)t * 266 + col] * SC - m);
                s += e;
                pwrow[col] = __float2bfloat16(e);
            }
        invs[t] = 1.f / s;
    }
    __syncthreads();

    // ---------------- phase 3: assemble GEMM ----------------
    for (int half = 0; half < 2; half++) {
        const int cbase = half * 256;
        #pragma unroll
        for (int a = 0; a < 2; a++)
            #pragma unroll
            for (int b = 0; b < 8; b++)
                #pragma unroll
                for (int c = 0; c < 4; c++) acc[a][b][c] = 0.f;

        auto issue3 = [&](int kk) {
            const uint32_t st = sbX + (kk % 3) * 16384;
            #pragma unroll
            for (int i = 0; i < 4; i++) {
                int idx = t + i * 256;
                int row = idx >> 5, ch = idx & 31;
                int hp = kk * 32 + row;
                int hy = h0 + (hp >> 4) - DD, hx = w0 + (hp & 15) - DD;
                bool ok = (hy >= 0 && hy < HDIM && hx >= 0 && hx < WDIM);
                const __nv_bfloat16* src = gphi +
                    (ok ? (((size_t)n * PIX + hy * WDIM + hx) * 1024 + cbase + ch * 8) : 0);
                CP_ASYNC16Z(st + row * 512 + ((ch ^ (row & 7)) << 4), src, ok ? 16u : 0u);
            }
            CP_COMMIT();
        };

        issue3(0); issue3(1);
        for (int kk = 0; kk < 8; kk++) {
            if (kk < 7) CP_WAIT(1); else CP_WAIT(0);
            __syncthreads();
            if (kk + 2 < 8) issue3(kk + 2);
            const uint32_t st = sbX + (kk % 3) * 16384;
            #pragma unroll
            for (int kh = 0; kh < 2; kh++) {
                uint32_t af[2][4], bm[4][4];
                const int chunk = kk * 4 + kh * 2 + cs;
                #pragma unroll
                for (int mi = 0; mi < 2; mi++)
                    LDSM4(af[mi], sbPW + (warp_m * 32 + mi * 16 + rl) * 528 + chunk * 16);
                const int r = kh * 16 + rl;
                #pragma unroll
                for (int nf = 0; nf < 4; nf++) {
                    const int c16 = warp_n * 8 + nf * 2 + cs;
                    LDSM4T(bm[nf], st + r * 512 + ((c16 ^ (r & 7)) << 4));
                }
                #pragma unroll
                for (int mi = 0; mi < 2; mi++)
                    #pragma unroll
                    for (int nf = 0; nf < 4; nf++) {
                        MMA16816(acc[mi][2 * nf + 0], af[mi], bm[nf][0], bm[nf][1]);
                        MMA16816(acc[mi][2 * nf + 1], af[mi], bm[nf][2], bm[nf][3]);
                    }
            }
        }

        #pragma unroll
        for (int mi = 0; mi < 2; mi++)
            #pragma unroll
            for (int ni = 0; ni < 8; ni++) {
                const int r0 = warp_m * 32 + mi * 16 + (lane >> 2);
                const int cc = cbase + warp_n * 64 + ni * 8 + 2 * (lane & 3);
                #pragma unroll
                for (int hh = 0; hh < 2; hh++) {
                    const int px = r0 + hh * 8;
                    const float is = invs[px];
                    const size_t addr =
                        ((size_t)n * PIX + (h0 + (px >> 3)) * WDIM + (w0 + (px & 7))) * CINT + cc;
                    __nv_bfloat162 pk = __floats2bfloat162_rn(acc[mi][ni][2 * hh + 0] * is,
                                                              acc[mi][ni][2 * hh + 1] * is);
                    *(__nv_bfloat162*)(y + addr) = pk;
                }
            }
        __syncthreads();
    }
}

// ---------------------------------------------------------------------------
extern "C" void kernel_launch(void* const* d_in, const int* in_sizes, int n_in,
                              void* d_out, int out_size)
{
    (void)in_sizes; (void)n_in; (void)out_size;
    const float* x       = (const float*)d_in[0];
    const float* x_ref   = (const float*)d_in[1];
    const float* w_g     = (const float*)d_in[2];
    const float* b_g     = (const float*)d_in[3];
    const float* w_theta = (const float*)d_in[4];
    const float* b_theta = (const float*)d_in[5];
    const float* w_phi   = (const float*)d_in[6];
    const float* b_phi   = (const float*)d_in[7];
    const float* w_out   = (const float*)d_in[8];
    const float* b_out   = (const float*)d_in[9];
    float* out = (float*)d_out;

    __nv_bfloat16 *xT_d, *xrT_d, *thb_d, *gphib_d, *ybf_d, *wth_d, *wgp_d, *wo_d;
    cudaGetSymbolAddress((void**)&xT_d,    g_xT);
    cudaGetSymbolAddress((void**)&xrT_d,   g_xrT);
    cudaGetSymbolAddress((void**)&thb_d,   g_thb);
    cudaGetSymbolAddress((void**)&gphib_d, g_gphib);
    cudaGetSymbolAddress((void**)&ybf_d,   g_ybf);
    cudaGetSymbolAddress((void**)&wth_d,   g_wth);
    cudaGetSymbolAddress((void**)&wgp_d,   g_wgp);
    cudaGetSymbolAddress((void**)&wo_d,    g_wo);

    const int FUSED_SMEM = 33792 + 68096 + 256;   // 102144
    const int GEMM_SMEM  = 2 * 49152;             // 98304
    cudaFuncSetAttribute(fused_attn_k, cudaFuncAttributeMaxDynamicSharedMemorySize, FUSED_SMEM);
    cudaFuncSetAttribute(proj_gemm,   cudaFuncAttributeMaxDynamicSharedMemorySize, GEMM_SMEM);
    cudaFuncSetAttribute(final_gemm,  cudaFuncAttributeMaxDynamicSharedMemorySize, GEMM_SMEM);

    // 1: all weight conversions in one launch
    cvt4_k<<<8192, 256>>>(w_theta, w_g, w_phi, w_out,
                          wth_d, wgp_d, wgp_d + (size_t)CINT * CINF, wo_d);

    // 2: transpose+convert both inputs NCHW fp32 -> [p][1024] bf16
    conv_tr2_k<<<dim3(PIX / 32, CINF / 64, 2 * NB), dim3(32, 8)>>>(x, x_ref, xT_d, xrT_d);

    // 3: merged theta + (g;phi) projections -> bf16 NHWC
    proj_gemm<<<dim3(36, 12, NB), 256, GEMM_SMEM>>>(
        wth_d, wgp_d, xT_d, xrT_d, b_theta, b_g, b_phi, thb_d, gphib_d);

    // 4: fused corr + softmax + assemble -> y bf16 [p][512]
    fused_attn_k<<<dim3(12, 12, NB), 256, FUSED_SMEM>>>(thb_d, gphib_d, ybf_d);

    // 5: out = x + w_out @ y + b_out (fp32 NCHW)
    final_gemm<<<dim3(36, 8, NB), 256, GEMM_SMEM>>>(wo_d, ybf_d, b_out, out, x);
}

// round 10
// speedup vs baseline: 1.1255x; 1.1255x over previous
#include <cuda_runtime.h>
#include <cuda_bf16.h>
#include <cstdint>
#include <math.h>

#define HDIM 96
#define WDIM 96
#define PIX  (HDIM*WDIM)     // 9216
#define NB   4
#define CINF 1024
#define CINT 512
#define DD   4
#define QD   9
#define QQ   81
#define NPIX (NB*PIX)        // 36864

// ------------------------- scratch (device globals) -------------------------
__device__ __nv_bfloat16 g_xT  [(size_t)NPIX * CINF];      // bf16 [p][1024]
__device__ __nv_bfloat16 g_xrT [(size_t)NPIX * CINF];      // bf16 [p][1024]
__device__ __nv_bfloat16 g_thb [(size_t)NPIX * CINT];      // bf16 theta NHWC [p][512]
__device__ __nv_bfloat16 g_gphib[(size_t)NPIX * 2 * CINT]; // bf16 g|phi NHWC [p][1024]
__device__ __nv_bfloat16 g_ybf [(size_t)NPIX * CINT];      // bf16 y NHWC [p][512]
__device__ __nv_bfloat16 g_wth [(size_t)CINT * CINF];
__device__ __nv_bfloat16 g_wgp [(size_t)CINF * CINF];      // (wg;wphi)
__device__ __nv_bfloat16 g_wo  [(size_t)CINF * CINT];

// ------------------------- helpers ------------------------------------------
__device__ __forceinline__ uint32_t smem_u32(const void* p) {
    uint32_t a;
    asm("{ .reg .u64 t; cvta.to.shared.u64 t, %1; cvt.u32.u64 %0, t; }" : "=r"(a) : "l"(p));
    return a;
}
#define CP_ASYNC16(dst, src) \
    asm volatile("cp.async.cg.shared.global [%0], [%1], 16;" :: "r"(dst), "l"(src))
#define CP_ASYNC16Z(dst, src, sz) \
    asm volatile("cp.async.cg.shared.global [%0], [%1], 16, %2;" :: "r"(dst), "l"(src), "r"(sz))
#define CP_COMMIT() asm volatile("cp.async.commit_group;" ::: "memory")
#define CP_WAIT(n)  asm volatile("cp.async.wait_group %0;" :: "n"(n) : "memory")

#define LDSM4(r, a) \
    asm volatile("ldmatrix.sync.aligned.m8n8.x4.shared.b16 {%0,%1,%2,%3}, [%4];" \
        : "=r"((r)[0]), "=r"((r)[1]), "=r"((r)[2]), "=r"((r)[3]) : "r"(a))
#define LDSM4T(r, a) \
    asm volatile("ldmatrix.sync.aligned.m8n8.x4.trans.shared.b16 {%0,%1,%2,%3}, [%4];" \
        : "=r"((r)[0]), "=r"((r)[1]), "=r"((r)[2]), "=r"((r)[3]) : "r"(a))

#define MMA16816(d, a, bb0, bb1) \
    asm volatile("mma.sync.aligned.m16n8k16.row.col.f32.bf16.bf16.f32 " \
        "{%0,%1,%2,%3},{%4,%5,%6,%7},{%8,%9},{%0,%1,%2,%3};" \
        : "+f"((d)[0]), "+f"((d)[1]), "+f"((d)[2]), "+f"((d)[3]) \
        : "r"((a)[0]), "r"((a)[1]), "r"((a)[2]), "r"((a)[3]), "r"(bb0), "r"(bb1))

// 32-bf16-wide tile swizzle (64B rows) — fused kernel phase 1
__device__ __forceinline__ uint32_t sw_off(int row, int ch) {
    return (uint32_t)(row * 64 + ((ch ^ ((row >> 1) & 3)) << 4));
}
// 64-bf16-wide tile swizzle (128B rows) — GEMM stages
__device__ __forceinline__ uint32_t sw128(int row, int ch) {
    return (uint32_t)(row * 128 + ((ch ^ (row & 7)) << 4));
}

// ------------------------- transpose + convert (x & x_ref merged) ------------
__global__ void conv_tr2_k(const float* __restrict__ x, const float* __restrict__ xr,
                           __nv_bfloat16* __restrict__ dx, __nv_bfloat16* __restrict__ dxr)
{
    __shared__ float ts[64][33];
    const int tx = threadIdx.x, ty = threadIdx.y;
    const int z = blockIdx.z;
    const int n = z & (NB - 1);
    const float* src = (z < NB) ? x : xr;
    __nv_bfloat16* dst = (z < NB) ? dx : dxr;
    const int p0 = blockIdx.x * 32, c0 = blockIdx.y * 64;
    #pragma unroll
    for (int r = 0; r < 8; r++) {
        int cl = ty + r * 8;
        ts[cl][tx] = src[((size_t)n * CINF + c0 + cl) * PIX + p0 + tx];
    }
    __syncthreads();
    #pragma unroll
    for (int r = 0; r < 4; r++) {
        int pl = ty + r * 8;
        __nv_bfloat162 v = __floats2bfloat162_rn(ts[2 * tx][pl], ts[2 * tx + 1][pl]);
        *(__nv_bfloat162*)(dst + ((size_t)n * PIX + p0 + pl) * CINF + c0 + 2 * tx) = v;
    }
}

// all four weight tensors are 524288 elements each
__global__ void cvt4_k(const float* __restrict__ s0, const float* __restrict__ s1,
                       const float* __restrict__ s2, const float* __restrict__ s3,
                       __nv_bfloat16* __restrict__ d0, __nv_bfloat16* __restrict__ d1,
                       __nv_bfloat16* __restrict__ d2, __nv_bfloat16* __restrict__ d3)
{
    int i = blockIdx.x * 256 + threadIdx.x;
    int seg = i >> 19, off = i & 524287;
    const float* s = (seg == 0) ? s0 : (seg == 1) ? s1 : (seg == 2) ? s2 : s3;
    __nv_bfloat16* d = (seg == 0) ? d0 : (seg == 1) ? d1 : (seg == 2) ? d2 : d3;
    d[off] = __float2bfloat16(s[off]);
}

// ------------------------- merged projection GEMM ----------------------------
// blockIdx.y < 4 : theta = w_theta @ x   -> thb  [p][512]
// blockIdx.y >= 4: (g;phi) = wgp @ x_ref -> gphib [p][1024]
// 128x128 tile, K-chunk 64, 2-stage cp.async (64KB dyn smem), 8 warps, 2 CTA/SM.
__global__ __launch_bounds__(256, 2)
void proj_gemm(const __nv_bfloat16* __restrict__ wth, const __nv_bfloat16* __restrict__ wgp,
               const __nv_bfloat16* __restrict__ xT, const __nv_bfloat16* __restrict__ xrT,
               const float* __restrict__ bth, const float* __restrict__ bg,
               const float* __restrict__ bphi,
               __nv_bfloat16* __restrict__ thb, __nv_bfloat16* __restrict__ gphib)
{
    extern __shared__ char smem[];   // 2 stages x (A 16KB | B 16KB)

    const int t = threadIdx.x, lane = t & 31, wid = t >> 5;
    const int warp_m = wid >> 2, warp_n = wid & 3;
    const int n = blockIdx.z, pbase = blockIdx.x * 128;
    const int by = blockIdx.y;
    const bool th = (by < 4);
    const int obase = (th ? by : by - 4) * 128;
    const __nv_bfloat16* A  = th ? wth : wgp;
    const __nv_bfloat16* Bx = th ? xT : xrT;
    __nv_bfloat16* out = th ? thb : gphib;
    const int ldo = th ? CINT : 2 * CINT;
    const float* b0 = th ? bth : bg;
    const float* b1 = th ? bth : bphi;
    const int K = CINF, NC = K >> 6;   // 16

    const __nv_bfloat16* Ab = A + (size_t)obase * K;
    const __nv_bfloat16* Bb = Bx + ((size_t)n * PIX + pbase) * K;
    const uint32_t sbase = smem_u32(smem);

    float acc[4][4][4];
    #pragma unroll
    for (int mi = 0; mi < 4; mi++)
        #pragma unroll
        for (int ni = 0; ni < 4; ni++)
            #pragma unroll
            for (int r = 0; r < 4; r++) acc[mi][ni][r] = 0.f;

    const int rowL = t >> 3, chL = t & 7;   // load mapping: 4 iters cover 128 rows
    auto issue = [&](int c) {
        const int k0 = c << 6;
        const uint32_t st = sbase + (c & 1) * 32768;
        #pragma unroll
        for (int i = 0; i < 4; i++) {
            int row = rowL + i * 32;
            CP_ASYNC16(st + sw128(row, chL), Ab + (size_t)row * K + k0 + chL * 8);
        }
        #pragma unroll
        for (int i = 0; i < 4; i++) {
            int row = rowL + i * 32;
            CP_ASYNC16(st + 16384 + sw128(row, chL), Bb + (size_t)row * K + k0 + chL * 8);
        }
        CP_COMMIT();
    };

    issue(0);
    const int rl = lane & 15, cs = lane >> 4;

    for (int c = 0; c < NC; c++) {
        CP_WAIT(0);
        __syncthreads();
        if (c + 1 < NC) issue(c + 1);

        const uint32_t stA = sbase + (c & 1) * 32768;
        const uint32_t stB = stA + 16384;
        #pragma unroll
        for (int kh = 0; kh < 4; kh++) {
            const int ch = 2 * kh + cs;
            uint32_t af[4][4], bf[2][4];
            #pragma unroll
            for (int mi = 0; mi < 4; mi++)
                LDSM4(af[mi], stA + sw128(warp_m * 64 + mi * 16 + rl, ch));
            #pragma unroll
            for (int g = 0; g < 2; g++)
                LDSM4(bf[g], stB + sw128(warp_n * 32 + g * 16 + rl, ch));
            #pragma unroll
            for (int mi = 0; mi < 4; mi++)
                #pragma unroll
                for (int g = 0; g < 2; g++) {
                    MMA16816(acc[mi][2 * g + 0], af[mi], bf[g][0], bf[g][2]);
                    MMA16816(acc[mi][2 * g + 1], af[mi], bf[g][1], bf[g][3]);
                }
        }
    }

    // epilogue: transpose via SMEM -> coalesced bf16 NHWC rows
    __syncthreads();
    __nv_bfloat16* S = (__nv_bfloat16*)smem;   // [128 p][136 o]
    #pragma unroll
    for (int mi = 0; mi < 4; mi++) {
        #pragma unroll
        for (int h = 0; h < 2; h++) {
            const int ol = warp_m * 64 + mi * 16 + (lane >> 2) + h * 8;
            const int og = obase + ol;
            const float bias = (og < CINT) ? b0[og] : b1[og - CINT];
            #pragma unroll
            for (int ni = 0; ni < 4; ni++) {
                const int pl = warp_n * 32 + ni * 8 + (lane & 3) * 2;
                S[(size_t)pl * 136 + ol]       = __float2bfloat16(acc[mi][ni][2 * h + 0] + bias);
                S[(size_t)(pl + 1) * 136 + ol] = __float2bfloat16(acc[mi][ni][2 * h + 1] + bias);
            }
        }
    }
    __syncthreads();
    #pragma unroll
    for (int s = 0; s < 16; s++) {
        const int pl = s * 8 + wid;
        uint2 v = *(uint2*)&S[(size_t)pl * 136 + lane * 4];
        *(uint2*)(out + ((size_t)n * PIX + pbase + pl) * ldo + obase + lane * 4) = v;
    }
}

// ------------------------- final GEMM (residual, fp32 NCHW) ------------------
// out[(n*CINF+o)*PIX + p] = sum_k wo[o][k]*y[p][k] + b[o] + resid[same]
__global__ __launch_bounds__(256, 2)
void final_gemm(const __nv_bfloat16* __restrict__ A, const __nv_bfloat16* __restrict__ B,
                const float* __restrict__ b0, float* __restrict__ out,
                const float* __restrict__ resid)
{
    extern __shared__ char smem[];   // 2 stages x 32KB

    const int t = threadIdx.x, lane = t & 31, wid = t >> 5;
    const int warp_m = wid >> 2, warp_n = wid & 3;
    const int n = blockIdx.z, pbase = blockIdx.x * 128, obase = blockIdx.y * 128;
    const int K = CINT, NC = K >> 6;   // 8

    const __nv_bfloat16* Ab = A + (size_t)obase * K;
    const __nv_bfloat16* Bb = B + ((size_t)n * PIX + pbase) * K;
    const uint32_t sbase = smem_u32(smem);

    float acc[4][4][4];
    #pragma unroll
    for (int mi = 0; mi < 4; mi++)
        #pragma unroll
        for (int ni = 0; ni < 4; ni++)
            #pragma unroll
            for (int r = 0; r < 4; r++) acc[mi][ni][r] = 0.f;

    const int rowL = t >> 3, chL = t & 7;
    auto issue = [&](int c) {
        const int k0 = c << 6;
        const uint32_t st = sbase + (c & 1) * 32768;
        #pragma unroll
        for (int i = 0; i < 4; i++) {
            int row = rowL + i * 32;
            CP_ASYNC16(st + sw128(row, chL), Ab + (size_t)row * K + k0 + chL * 8);
        }
        #pragma unroll
        for (int i = 0; i < 4; i++) {
            int row = rowL + i * 32;
            CP_ASYNC16(st + 16384 + sw128(row, chL), Bb + (size_t)row * K + k0 + chL * 8);
        }
        CP_COMMIT();
    };

    issue(0);
    const int rl = lane & 15, cs = lane >> 4;

    for (int c = 0; c < NC; c++) {
        CP_WAIT(0);
        __syncthreads();
        if (c + 1 < NC) issue(c + 1);

        const uint32_t stA = sbase + (c & 1) * 32768;
        const uint32_t stB = stA + 16384;
        #pragma unroll
        for (int kh = 0; kh < 4; kh++) {
            const int ch = 2 * kh + cs;
            uint32_t af[4][4], bf[2][4];
            #pragma unroll
            for (int mi = 0; mi < 4; mi++)
                LDSM4(af[mi], stA + sw128(warp_m * 64 + mi * 16 + rl, ch));
            #pragma unroll
            for (int g = 0; g < 2; g++)
                LDSM4(bf[g], stB + sw128(warp_n * 32 + g * 16 + rl, ch));
            #pragma unroll
            for (int mi = 0; mi < 4; mi++)
                #pragma unroll
                for (int g = 0; g < 2; g++) {
                    MMA16816(acc[mi][2 * g + 0], af[mi], bf[g][0], bf[g][2]);
                    MMA16816(acc[mi][2 * g + 1], af[mi], bf[g][1], bf[g][3]);
                }
        }
    }

    // epilogue: stage to SMEM, then fully-coalesced resid add + store
    float* Es = (float*)smem;   // [64 o][132 p]
    #pragma unroll
    for (int og = 0; og < 2; og++) {
        __syncthreads();
        if (warp_m == og) {
            #pragma unroll
            for (int mi = 0; mi < 4; mi++)
                #pragma unroll
                for (int h = 0; h < 2; h++) {
                    const int row = mi * 16 + (lane >> 2) + h * 8;
                    #pragma unroll
                    for (int ni = 0; ni < 4; ni++) {
                        const int col = warp_n * 32 + ni * 8 + (lane & 3) * 2;
                        Es[(size_t)row * 132 + col]     = acc[mi][ni][2 * h + 0];
                        Es[(size_t)row * 132 + col + 1] = acc[mi][ni][2 * h + 1];
                    }
                }
        }
        __syncthreads();
        #pragma unroll
        for (int s = 0; s < 8; s++) {
            const int row = s * 8 + wid;
            const int o = obase + og * 64 + row;
            const size_t addr = ((size_t)n * CINF + o) * PIX + pbase + lane * 4;
            float4 e = *(float4*)&Es[(size_t)row * 132 + lane * 4];
            float4 r = *(const float4*)(resid + addr);
            const float bias = b0[o];
            float4 v;
            v.x = e.x + bias + r.x; v.y = e.y + bias + r.y;
            v.z = e.z + bias + r.z; v.w = e.w + bias + r.w;
            *(float4*)(out + addr) = v;
        }
    }
}

// ------------------------- fused corr + softmax + assemble -------------------
// (unchanged — passed three times)
__global__ __launch_bounds__(256, 2)
void fused_attn_k(const __nv_bfloat16* __restrict__ theta,
                  const __nv_bfloat16* __restrict__ gphi,
                  __nv_bfloat16* __restrict__ y)
{
    extern __shared__ char smem[];
    char*  Xr   = smem + 33792;
    float* Cs   = (float*)Xr;                       // [64][266] fp32
    float* invs = (float*)(smem + 33792 + 68096);   // [64]

    const int t = threadIdx.x, lane = t & 31, wid = t >> 5;
    const int warp_m = wid >> 2, warp_n = wid & 3;  // 2 x 4
    const int rl = lane & 15, cs = lane >> 4;
    const int n = blockIdx.z, h0 = blockIdx.y * 8, w0 = blockIdx.x * 8;

    const uint32_t sbX  = smem_u32(Xr);
    const uint32_t sbPW = smem_u32(smem);

    float acc[2][8][4];
    #pragma unroll
    for (int a = 0; a < 2; a++)
        #pragma unroll
        for (int b = 0; b < 8; b++)
            #pragma unroll
            for (int c = 0; c < 4; c++) acc[a][b][c] = 0.f;

    // ---------------- phase 1: corr GEMM ----------------
    const int rowA = t >> 2, chA = t & 3;
    const __nv_bfloat16* thsrc =
        theta + ((size_t)n * PIX + (h0 + (rowA >> 3)) * WDIM + (w0 + (rowA & 7))) * CINT + chA * 8;

    const __nv_bfloat16* phsrc[4];
    uint32_t phok[4]; int phrow[4], phch[4];
    #pragma unroll
    for (int i = 0; i < 4; i++) {
        int idx = t + i * 256;
        int row = idx >> 2, ch = idx & 3;
        int hy = h0 + (row >> 4) - DD, hx = w0 + (row & 15) - DD;
        bool ok = (hy >= 0 && hy < HDIM && hx >= 0 && hx < WDIM);
        phrow[i] = row; phch[i] = ch; phok[i] = ok ? 16u : 0u;
        phsrc[i] = gphi + (ok ? (((size_t)n * PIX + hy * WDIM + hx) * 1024 + 512 + ch * 8) : 0);
    }

    auto issue1 = [&](int c) {
        const int c0 = c << 5;
        const uint32_t st = sbX + (c % 3) * 20480;
        CP_ASYNC16(st + sw_off(rowA, chA), thsrc + c0);
        #pragma unroll
        for (int i = 0; i < 4; i++)
            CP_ASYNC16Z(st + 4096 + sw_off(phrow[i], phch[i]),
                        phsrc[i] + (phok[i] ? c0 : 0), phok[i]);
        CP_COMMIT();
    };

    issue1(0); issue1(1);
    for (int c = 0; c < 16; c++) {
        if (c < 15) CP_WAIT(1); else CP_WAIT(0);
        __syncthreads();
        if (c + 2 < 16) issue1(c + 2);
        const uint32_t stA = sbX + (c % 3) * 20480;
        const uint32_t stB = stA + 4096;
        #pragma unroll
        for (int kh = 0; kh < 2; kh++) {
            const int ch = 2 * kh + cs;
            uint32_t af[2][4], bm[4][4];
            #pragma unroll
            for (int mi = 0; mi < 2; mi++)
                LDSM4(af[mi], stA + sw_off(warp_m * 32 + mi * 16 + rl, ch));
            #pragma unroll
            for (int nf = 0; nf < 4; nf++)
                LDSM4(bm[nf], stB + sw_off(warp_n * 64 + nf * 16 + rl, ch));
            #pragma unroll
            for (int mi = 0; mi < 2; mi++)
                #pragma unroll
                for (int nf = 0; nf < 4; nf++) {
                    MMA16816(acc[mi][2 * nf + 0], af[mi], bm[nf][0], bm[nf][2]);
                    MMA16816(acc[mi][2 * nf + 1], af[mi], bm[nf][1], bm[nf][3]);
                }
        }
    }
    __syncthreads();   // stages dead; write C to smem (overlays stage region)

    #pragma unroll
    for (int mi = 0; mi < 2; mi++)
        #pragma unroll
        for (int ni = 0; ni < 8; ni++) {
            const int r0  = warp_m * 32 + mi * 16 + (lane >> 2);
            const int col = warp_n * 64 + ni * 8 + 2 * (lane & 3);
            *(float2*)&Cs[(size_t)r0 * 266 + col]       = make_float2(acc[mi][ni][0], acc[mi][ni][1]);
            *(float2*)&Cs[(size_t)(r0 + 8) * 266 + col] = make_float2(acc[mi][ni][2], acc[mi][ni][3]);
        }
    __syncthreads();

    // ---------------- phase 2: softmax -> PW bf16 ----------------
    if (t < 64) {
        const int py = t >> 3, pxx = t & 7;
        uint32_t* pwz = (uint32_t*)(smem + t * 528);
        #pragma unroll 4
        for (int i = 0; i < 132; i++) pwz[i] = 0;
        const float SC = 0.051031036307982884f;   // 256/(512*sqrt(96))
        float m = -1e30f;
        #pragma unroll
        for (int dy = 0; dy < QD; dy++)
            #pragma unroll
            for (int dx = 0; dx < QD; dx++)
                m = fmaxf(m, Cs[(size_t)t * 266 + (py + dy) * 16 + pxx + dx] * SC);
        float s = 0.f;
        __nv_bfloat16* pwrow = (__nv_bfloat16*)(smem + t * 528);
        #pragma unroll
        for (int dy = 0; dy < QD; dy++)
            #pragma unroll
            for (int dx = 0; dx < QD; dx++) {
                const int col = (py + dy) * 16 + pxx + dx;
                float e = __expf(Cs[(size_t)t * 266 + col] * SC - m);
                s += e;
                pwrow[col] = __float2bfloat16(e);
            }
        invs[t] = 1.f / s;
    }
    __syncthreads();

    // ---------------- phase 3: assemble GEMM ----------------
    for (int half = 0; half < 2; half++) {
        const int cbase = half * 256;
        #pragma unroll
        for (int a = 0; a < 2; a++)
            #pragma unroll
            for (int b = 0; b < 8; b++)
                #pragma unroll
                for (int c = 0; c < 4; c++) acc[a][b][c] = 0.f;

        auto issue3 = [&](int kk) {
            const uint32_t st = sbX + (kk % 3) * 16384;
            #pragma unroll
            for (int i = 0; i < 4; i++) {
                int idx = t + i * 256;
                int row = idx >> 5, ch = idx & 31;
                int hp = kk * 32 + row;
                int hy = h0 + (hp >> 4) - DD, hx = w0 + (hp & 15) - DD;
                bool ok = (hy >= 0 && hy < HDIM && hx >= 0 && hx < WDIM);
                const __nv_bfloat16* src = gphi +
                    (ok ? (((size_t)n * PIX + hy * WDIM + hx) * 1024 + cbase + ch * 8) : 0);
                CP_ASYNC16Z(st + row * 512 + ((ch ^ (row & 7)) << 4), src, ok ? 16u : 0u);
            }
            CP_COMMIT();
        };

        issue3(0); issue3(1);
        for (int kk = 0; kk < 8; kk++) {
            if (kk < 7) CP_WAIT(1); else CP_WAIT(0);
            __syncthreads();
            if (kk + 2 < 8) issue3(kk + 2);
            const uint32_t st = sbX + (kk % 3) * 16384;
            #pragma unroll
            for (int kh = 0; kh < 2; kh++) {
                uint32_t af[2][4], bm[4][4];
                const int chunk = kk * 4 + kh * 2 + cs;
                #pragma unroll
                for (int mi = 0; mi < 2; mi++)
                    LDSM4(af[mi], sbPW + (warp_m * 32 + mi * 16 + rl) * 528 + chunk * 16);
                const int r = kh * 16 + rl;
                #pragma unroll
                for (int nf = 0; nf < 4; nf++) {
                    const int c16 = warp_n * 8 + nf * 2 + cs;
                    LDSM4T(bm[nf], st + r * 512 + ((c16 ^ (r & 7)) << 4));
                }
                #pragma unroll
                for (int mi = 0; mi < 2; mi++)
                    #pragma unroll
                    for (int nf = 0; nf < 4; nf++) {
                        MMA16816(acc[mi][2 * nf + 0], af[mi], bm[nf][0], bm[nf][1]);
                        MMA16816(acc[mi][2 * nf + 1], af[mi], bm[nf][2], bm[nf][3]);
                    }
            }
        }

        #pragma unroll
        for (int mi = 0; mi < 2; mi++)
            #pragma unroll
            for (int ni = 0; ni < 8; ni++) {
                const int r0 = warp_m * 32 + mi * 16 + (lane >> 2);
                const int cc = cbase + warp_n * 64 + ni * 8 + 2 * (lane & 3);
                #pragma unroll
                for (int hh = 0; hh < 2; hh++) {
                    const int px = r0 + hh * 8;
                    const float is = invs[px];
                    const size_t addr =
                        ((size_t)n * PIX + (h0 + (px >> 3)) * WDIM + (w0 + (px & 7))) * CINT + cc;
                    __nv_bfloat162 pk = __floats2bfloat162_rn(acc[mi][ni][2 * hh + 0] * is,
                                                              acc[mi][ni][2 * hh + 1] * is);
                    *(__nv_bfloat162*)(y + addr) = pk;
                }
            }
        __syncthreads();
    }
}

// ---------------------------------------------------------------------------
extern "C" void kernel_launch(void* const* d_in, const int* in_sizes, int n_in,
                              void* d_out, int out_size)
{
    (void)in_sizes; (void)n_in; (void)out_size;
    const float* x       = (const float*)d_in[0];
    const float* x_ref   = (const float*)d_in[1];
    const float* w_g     = (const float*)d_in[2];
    const float* b_g     = (const float*)d_in[3];
    const float* w_theta = (const float*)d_in[4];
    const float* b_theta = (const float*)d_in[5];
    const float* w_phi   = (const float*)d_in[6];
    const float* b_phi   = (const float*)d_in[7];
    const float* w_out   = (const float*)d_in[8];
    const float* b_out   = (const float*)d_in[9];
    float* out = (float*)d_out;

    __nv_bfloat16 *xT_d, *xrT_d, *thb_d, *gphib_d, *ybf_d, *wth_d, *wgp_d, *wo_d;
    cudaGetSymbolAddress((void**)&xT_d,    g_xT);
    cudaGetSymbolAddress((void**)&xrT_d,   g_xrT);
    cudaGetSymbolAddress((void**)&thb_d,   g_thb);
    cudaGetSymbolAddress((void**)&gphib_d, g_gphib);
    cudaGetSymbolAddress((void**)&ybf_d,   g_ybf);
    cudaGetSymbolAddress((void**)&wth_d,   g_wth);
    cudaGetSymbolAddress((void**)&wgp_d,   g_wgp);
    cudaGetSymbolAddress((void**)&wo_d,    g_wo);

    const int FUSED_SMEM = 33792 + 68096 + 256;   // 102144
    const int GEMM_SMEM  = 2 * 32768;             // 65536
    cudaFuncSetAttribute(fused_attn_k, cudaFuncAttributeMaxDynamicSharedMemorySize, FUSED_SMEM);
    cudaFuncSetAttribute(proj_gemm,   cudaFuncAttributeMaxDynamicSharedMemorySize, GEMM_SMEM);
    cudaFuncSetAttribute(final_gemm,  cudaFuncAttributeMaxDynamicSharedMemorySize, GEMM_SMEM);

    // 1: all weight conversions in one launch
    cvt4_k<<<8192, 256>>>(w_theta, w_g, w_phi, w_out,
                          wth_d, wgp_d, wgp_d + (size_t)CINT * CINF, wo_d);

    // 2: transpose+convert both inputs NCHW fp32 -> [p][1024] bf16
    conv_tr2_k<<<dim3(PIX / 32, CINF / 64, 2 * NB), dim3(32, 8)>>>(x, x_ref, xT_d, xrT_d);

    // 3: merged theta + (g;phi) projections -> bf16 NHWC
    proj_gemm<<<dim3(72, 12, NB), 256, GEMM_SMEM>>>(
        wth_d, wgp_d, xT_d, xrT_d, b_theta, b_g, b_phi, thb_d, gphib_d);

    // 4: fused corr + softmax + assemble -> y bf16 [p][512]
    fused_attn_k<<<dim3(12, 12, NB), 256, FUSED_SMEM>>>(thb_d, gphib_d, ybf_d);

    // 5: out = x + w_out @ y + b_out (fp32 NCHW)
    final_gemm<<<dim3(72, 8, NB), 256, GEMM_SMEM>>>(wo_d, ybf_d, b_out, out, x);
}